// round 2
// baseline (speedup 1.0000x reference)
#include <cuda_runtime.h>
#include <cuda_fp16.h>
#include <cstdint>
#include <cstddef>

// ---------------- problem constants ----------------
#define TOKENS 8192
#define IN_F   4096
#define OUT_F  11008

// ---------------- GEMM tiling ----------------
#define BM 128
#define BN 256
#define BK 64
#define STAGES 4
#define KITERS (IN_F / BK)          // 64

#define SMEM_STAGE_A (BM * BK * 2)  // 16384 B
#define SMEM_STAGE_B (BN * BK * 2)  // 32768 B
#define SMEM_STAGE   (SMEM_STAGE_A + SMEM_STAGE_B)   // 49152
#define SMEM_BYTES   (STAGES * SMEM_STAGE)           // 196608

// ---------------- scratch (static device globals; no allocation) ----------------
__device__ __align__(1024) __half g_W[(size_t)OUT_F * IN_F];  // W^T: [n][k], 90 MB
__device__ __align__(1024) __half g_X[(size_t)TOKENS * IN_F]; // x fp16: [m][k], 67 MB

// ---------------- PTX helpers (all baseline sm_80+: cp.async, ldmatrix, mma.sync) ----
__device__ __forceinline__ uint32_t smem_u32(const void* p) {
    uint32_t a;
    asm("{ .reg .u64 t; cvta.to.shared.u64 t, %1; cvt.u32.u64 %0, t; }" : "=r"(a) : "l"(p));
    return a;
}
__device__ __forceinline__ void cp_async16(uint32_t dst, const void* src) {
    asm volatile("cp.async.cg.shared.global [%0], [%1], 16;" :: "r"(dst), "l"(src) : "memory");
}
__device__ __forceinline__ void cp_commit() {
    asm volatile("cp.async.commit_group;" ::: "memory");
}
template <int N> __device__ __forceinline__ void cp_wait() {
    asm volatile("cp.async.wait_group %0;" :: "n"(N) : "memory");
}
__device__ __forceinline__ void ldsm_x4(uint32_t& r0, uint32_t& r1, uint32_t& r2, uint32_t& r3,
                                        uint32_t addr) {
    asm volatile("ldmatrix.sync.aligned.m8n8.x4.shared.b16 {%0,%1,%2,%3}, [%4];"
                 : "=r"(r0), "=r"(r1), "=r"(r2), "=r"(r3) : "r"(addr));
}
__device__ __forceinline__ void mma16816(float* c, const uint32_t* a, const uint32_t* b) {
    asm volatile(
        "mma.sync.aligned.m16n8k16.row.col.f32.f16.f16.f32 "
        "{%0,%1,%2,%3}, {%4,%5,%6,%7}, {%8,%9}, {%0,%1,%2,%3};"
        : "+f"(c[0]), "+f"(c[1]), "+f"(c[2]), "+f"(c[3])
        : "r"(a[0]), "r"(a[1]), "r"(a[2]), "r"(a[3]), "r"(b[0]), "r"(b[1]));
}

// SW128 swizzle on byte offset within a tile (128B rows)
#define SWZ(o) ((o) ^ (((o) >> 3) & 0x70))

// ---------------- kernel 1: dequant qweight -> fp16 W^T [n][k] ----------------
__global__ void __launch_bounds__(256) dequant_kernel(const int* __restrict__ qw,
                                                      const int* __restrict__ qz,
                                                      const float* __restrict__ sc) {
    int idx = blockIdx.x * blockDim.x + threadIdx.x;   // over (IN_F/8) * OUT_F, exact
    int kp = idx / OUT_F;            // packed-k row (0..511), n fast => coalesced qw read
    int n  = idx - kp * OUT_F;
    int g  = kp >> 4;                // group = (kp*8)/128
    uint32_t w  = (uint32_t)qw[(size_t)kp * OUT_F + n];
    uint32_t zw = (uint32_t)qz[g * (OUT_F / 8) + (n >> 3)];
    int   z = (int)((zw >> ((n & 7) * 4)) & 15);
    float s = sc[(size_t)g * OUT_F + n];
    union { __half2 h[4]; uint4 u; } r;
#pragma unroll
    for (int j = 0; j < 4; ++j) {
        int w0 = (int)((w >> (8 * j)) & 15);
        int w1 = (int)((w >> (8 * j + 4)) & 15);
        r.h[j] = __floats2half2_rn(s * (float)(w0 - z), s * (float)(w1 - z));
    }
    *(uint4*)(&g_W[((size_t)n << 12) + ((size_t)kp << 3)]) = r.u;
}

// ---------------- kernel 2: x fp32 -> fp16 ----------------
__global__ void __launch_bounds__(256) xconv_kernel(const float* __restrict__ x) {
    size_t i = (size_t)blockIdx.x * blockDim.x + threadIdx.x;  // over TOKENS*IN_F/4, exact
    float4 v = ((const float4*)x)[i];
    union { __half2 h[2]; uint2 u; } r;
    r.h[0] = __floats2half2_rn(v.x, v.y);
    r.h[1] = __floats2half2_rn(v.z, v.w);
    ((uint2*)g_X)[i] = r.u;
}

// ---------------- kernel 3: pipelined HMMA GEMM ----------------
__device__ __forceinline__ void load_stage(int kt, uint32_t aBase, uint32_t bBase,
                                           const __half* gA, const __half* gB, int tid) {
    const int k0 = kt * BK;
    // A tile: 128 rows x 128B (8 x 16B chunks) = 1024 chunks; 256 threads -> 4 each
#pragma unroll
    for (int it = 0; it < 4; ++it) {
        int chunk = tid + it * 256;
        int r = chunk >> 3, c = chunk & 7;
        cp_async16(aBase + SWZ((uint32_t)(r * 128 + c * 16)),
                   gA + (size_t)r * IN_F + k0 + c * 8);
    }
    // B tile: 256 rows x 128B = 2048 chunks; 8 each
#pragma unroll
    for (int it = 0; it < 8; ++it) {
        int chunk = tid + it * 256;
        int r = chunk >> 3, c = chunk & 7;
        cp_async16(bBase + SWZ((uint32_t)(r * 128 + c * 16)),
                   gB + (size_t)r * IN_F + k0 + c * 8);
    }
    cp_commit();
}

__global__ void __launch_bounds__(256, 1) gemm_kernel(const float* __restrict__ bias,
                                                      float* __restrict__ out) {
    extern __shared__ char dynsmem[];
    const int tid = threadIdx.x;
    const int wid = tid >> 5;
    const int lid = tid & 31;
    const int wm = wid & 1;       // warp m half (0/1)
    const int wn = wid >> 1;      // warp n quarter (0..3)
    const int m0 = blockIdx.x * BM;   // 64 m-tiles
    const int n0 = blockIdx.y * BN;   // 43 n-tiles

    uint32_t sbase = smem_u32(dynsmem);
    uint32_t aS[STAGES], bS[STAGES];
#pragma unroll
    for (int s = 0; s < STAGES; ++s) {
        aS[s] = sbase + s * SMEM_STAGE;
        bS[s] = aS[s] + SMEM_STAGE_A;
    }

    const __half* gA = g_X + (size_t)m0 * IN_F;
    const __half* gB = g_W + (size_t)n0 * IN_F;

    float acc[4][8][4];
#pragma unroll
    for (int mi = 0; mi < 4; ++mi)
#pragma unroll
        for (int ni = 0; ni < 8; ++ni)
#pragma unroll
            for (int q = 0; q < 4; ++q) acc[mi][ni][q] = 0.0f;

    // per-lane ldmatrix row/chunk components
    const int aRow = wm * 64 + (lid & 7) + ((lid >> 3) & 1) * 8;  // + mi*16
    const int aChk = (lid >> 4) & 1;                              // + 2*kk
    const int bRow = wn * 64 + (lid & 7) + ((lid >> 4) & 1) * 8;  // + nj*16
    const int bChk = (lid >> 3) & 1;                              // + 2*kk

    // prologue: fill STAGES-1 stages
#pragma unroll
    for (int s = 0; s < STAGES - 1; ++s) load_stage(s, aS[s], bS[s], gA, gB, tid);

    for (int j = 0; j < KITERS; ++j) {
        int rem = KITERS - 1 - j;
        if (rem >= 2)      cp_wait<STAGES - 2>();
        else if (rem == 1) cp_wait<1>();
        else               cp_wait<0>();
        __syncthreads();

        // issue loads for stage j+STAGES-1 (into slot whose compute finished last iter)
        int ls = j + STAGES - 1;
        if (ls < KITERS) load_stage(ls, aS[ls & (STAGES - 1)], bS[ls & (STAGES - 1)], gA, gB, tid);

        const uint32_t aT = aS[j & (STAGES - 1)];
        const uint32_t bT = bS[j & (STAGES - 1)];

#pragma unroll
        for (int kk = 0; kk < BK / 16; ++kk) {
            uint32_t a[4][4];
#pragma unroll
            for (int mi = 0; mi < 4; ++mi) {
                uint32_t ad = aT + SWZ((uint32_t)((aRow + mi * 16) * 128 + (2 * kk + aChk) * 16));
                ldsm_x4(a[mi][0], a[mi][1], a[mi][2], a[mi][3], ad);
            }
            uint32_t b[8][2];
#pragma unroll
            for (int nj = 0; nj < 4; ++nj) {
                uint32_t bd = bT + SWZ((uint32_t)((bRow + nj * 16) * 128 + (2 * kk + bChk) * 16));
                uint32_t r0, r1, r2, r3;
                ldsm_x4(r0, r1, r2, r3, bd);
                b[2 * nj][0] = r0; b[2 * nj][1] = r1;
                b[2 * nj + 1][0] = r2; b[2 * nj + 1][1] = r3;
            }
#pragma unroll
            for (int mi = 0; mi < 4; ++mi)
#pragma unroll
                for (int ni = 0; ni < 8; ++ni)
                    mma16816(acc[mi][ni], a[mi], b[ni]);
        }
    }

    // epilogue: direct stores with bias (D frag: lane l -> row l/4 (+8), col 2*(l%4))
    const int mw = m0 + wm * 64;
    const int nw = n0 + wn * 64;
    const int rsub = lid >> 2;
    const int csub = (lid & 3) * 2;
#pragma unroll
    for (int mi = 0; mi < 4; ++mi) {
#pragma unroll
        for (int ni = 0; ni < 8; ++ni) {
            int col = nw + ni * 8 + csub;
            float2 bv = *(const float2*)(bias + col);
            int r0 = mw + mi * 16 + rsub;
            float2 v0 = { acc[mi][ni][0] + bv.x, acc[mi][ni][1] + bv.y };
            *(float2*)(out + (size_t)r0 * OUT_F + col) = v0;
            float2 v1 = { acc[mi][ni][2] + bv.x, acc[mi][ni][3] + bv.y };
            *(float2*)(out + (size_t)(r0 + 8) * OUT_F + col) = v1;
        }
    }
}

// ---------------- launch ----------------
extern "C" void kernel_launch(void* const* d_in, const int* in_sizes, int n_in,
                              void* d_out, int out_size) {
    const float* x    = (const float*)d_in[0];
    const int*   qw   = (const int*)d_in[1];
    const int*   qz   = (const int*)d_in[2];
    const float* sc   = (const float*)d_in[3];
    const float* bias = (const float*)d_in[4];
    float* out = (float*)d_out;

    cudaFuncSetAttribute(gemm_kernel, cudaFuncAttributeMaxDynamicSharedMemorySize, SMEM_BYTES);

    // 1) dequantize W -> fp16 [n][k]
    {
        int total = (IN_F / 8) * OUT_F;           // 5,636,096 (multiple of 256)
        dequant_kernel<<<total / 256, 256>>>(qw, qz, sc);
    }
    // 2) x -> fp16
    {
        int total = (int)(((size_t)TOKENS * IN_F) / 4);  // 8,388,608
        xconv_kernel<<<total / 256, 256>>>(x);
    }
    // 3) GEMM + bias
    {
        dim3 grid(TOKENS / BM, OUT_F / BN);  // (64, 43)
        gemm_kernel<<<grid, 256, SMEM_BYTES>>>(bias, out);
    }
}